// round 14
// baseline (speedup 1.0000x reference)
#include <cuda_runtime.h>
#include <cuda_fp16.h>
#include <cstdint>

#define S_DIM 4
#define N_DIM 4096
#define D_DIM 64

// fp16 operand scratch, pair-packed along k: word = (h16 elem 2p | h16 elem 2p+1 << 16)
#define PAIR_WORDS (S_DIM * N_DIM * D_DIM / 2)
__device__ uint32_t g_Xf[PAIR_WORDS];   // x1 as fp16 pairs
__device__ uint32_t g_Qf[PAIR_WORDS];   // Q  as fp16 pairs

__device__ __forceinline__ uint32_t smem_u32(const void* p) {
    uint32_t a;
    asm("{ .reg .u64 t; cvta.to.shared.u64 t, %1; cvt.u32.u64 %0, t; }"
        : "=r"(a) : "l"(p));
    return a;
}
__device__ __forceinline__ uint32_t h2pack(float a, float b) {
    __half2 h = __floats2half2_rn(a, b);
    return *reinterpret_cast<uint32_t*>(&h);
}
// fp16 mma m16n8k16, fp32 accumulate (baseline PTX, valid on compute_103)
__device__ __forceinline__ void mma_fp16(float d[4], const uint32_t a[4], const uint32_t b[2]) {
    asm volatile(
        "mma.sync.aligned.m16n8k16.row.col.f32.f16.f16.f32 "
        "{%0,%1,%2,%3}, {%4,%5,%6,%7}, {%8,%9}, {%0,%1,%2,%3};"
        : "+f"(d[0]), "+f"(d[1]), "+f"(d[2]), "+f"(d[3])
        : "r"(a[0]), "r"(a[1]), "r"(a[2]), "r"(a[3]), "r"(b[0]), "r"(b[1]));
}
__device__ __forceinline__ void ldsm_x4(uint32_t r[4], uint32_t addr) {
    asm volatile("ldmatrix.sync.aligned.m8n8.x4.shared.b16 {%0,%1,%2,%3}, [%4];"
                 : "=r"(r[0]), "=r"(r[1]), "=r"(r[2]), "=r"(r[3]) : "r"(addr));
}
__device__ __forceinline__ void ldsm_x2(uint32_t r[2], uint32_t addr) {
    asm volatile("ldmatrix.sync.aligned.m8n8.x2.shared.b16 {%0,%1}, [%2];"
                 : "=r"(r[0]), "=r"(r[1]) : "r"(addr));
}

// ---------------------------------------------------------------------------
// Fused prep: blocks [0,256) compute Q (fp32 SIMT) -> fp16 pairs;
//             blocks [256,1280) convert x1 -> fp16 pairs.
// ---------------------------------------------------------------------------
__device__ __forceinline__ void load_tile_transposed64(
    const float* __restrict__ gsrc, float* sdst, int t)
{
    const float4* g4 = reinterpret_cast<const float4*>(gsrc);
#pragma unroll
    for (int p = 0; p < 4; ++p) {
        int f4 = p * 256 + t;
        int x  = f4 >> 4;
        int k4 = (f4 & 15) << 2;
        float4 v = g4[f4];
        float vv[4] = {v.x, v.y, v.z, v.w};
#pragma unroll
        for (int q = 0; q < 4; ++q) {
            int k  = k4 + q;
            int c4 = (x >> 2) ^ ((k >> 2) & 15);
            sdst[k * 64 + c4 * 4 + (x & 3)] = vv[q];
        }
    }
}

__global__ __launch_bounds__(256) void prep_kernel(
    const float* __restrict__ x0, const float* __restrict__ x1,
    const float* __restrict__ W)
{
    __shared__ float Xs[64 * 64];
    __shared__ float Ws[64 * 64];
    int t = threadIdx.x;

    if (blockIdx.x >= 256) {
        int i = (blockIdx.x - 256) * 256 + t;     // float4 index = uint2 pair index
        float4 v = reinterpret_cast<const float4*>(x1)[i];
        uint2 p;
        p.x = h2pack(v.x, v.y);
        p.y = h2pack(v.z, v.w);
        reinterpret_cast<uint2*>(g_Xf)[i] = p;
        return;
    }

    int r0 = blockIdx.x * 64;
    load_tile_transposed64(x0 + (size_t)r0 * 64, Xs, t);
    load_tile_transposed64(W, Ws, t);
    __syncthreads();

    int tx = t & 15, ty = t >> 4;
    float acc[4][4] = {};
#pragma unroll
    for (int k = 0; k < 64; ++k) {
        int sw = (k >> 2) & 15;
        float4 a = *reinterpret_cast<const float4*>(&Xs[k * 64 + ((ty ^ sw) << 2)]);
        float4 b = *reinterpret_cast<const float4*>(&Ws[k * 64 + ((tx ^ sw) << 2)]);
        float av[4] = {a.x, a.y, a.z, a.w};
        float bv[4] = {b.x, b.y, b.z, b.w};
#pragma unroll
        for (int ra = 0; ra < 4; ++ra)
#pragma unroll
            for (int rb = 0; rb < 4; ++rb)
                acc[ra][rb] += av[ra] * bv[rb];
    }

#pragma unroll
    for (int ra = 0; ra < 4; ++ra) {
        int r = r0 + ty * 4 + ra;
        uint2 p;
        p.x = h2pack(acc[ra][0], acc[ra][1]);
        p.y = h2pack(acc[ra][2], acc[ra][3]);
        *reinterpret_cast<uint2*>(&g_Qf[r * 32 + 2 * tx]) = p;
    }
}

// ---------------------------------------------------------------------------
// Stage 2: single-pass fp16 mma.sync GEMM, quarter-outer structure.
// CTA = 128x128 C tile, 256 threads = 8 warps (2m x 4n), warp = 64x32.
// Four quarter-phases (one mt each): compute 32 rows -> staged coalesced
// store, so each quarter's MMA overlaps the previous quarter's store drain.
// 16-reg accumulator -> 4 CTAs/SM (launch_bounds 64-reg cap).
// Smem: 2 operand tiles [128][36 pair-words] (36.9 KB) + stage 32x136 fp32
// (17.4 KB) = 54.3 KB; x4 CTAs = 217 KB.
// ---------------------------------------------------------------------------
#define PADW 36
#define TILE_W (128 * PADW)
#define STG_STRIDE 136                  // floats per staged row (bank-safe)
#define STAGE_FLOATS (32 * STG_STRIDE)
#define SMEM_DYN (2 * TILE_W * 4 + STAGE_FLOATS * 4)
#define A_MT_BYTES (16 * PADW * 4)      // 16 rows
#define B_NT_BYTES (8 * PADW * 4)       // 8 rows
#define KT_BYTES   32                   // 8 pair-words = 16 fp16

__device__ __forceinline__ void fill_tile_async(
    const uint32_t* __restrict__ gsrc, uint32_t* sdst, int t)
{
#pragma unroll
    for (int it = 0; it < 4; ++it) {
        int f4 = it * 256 + t;          // 0..1023 16B chunks (128 rows x 8)
        int r  = f4 >> 3;
        int c4 = f4 & 7;
        uint32_t sa = smem_u32(&sdst[r * PADW + c4 * 4]);
        asm volatile("cp.async.cg.shared.global [%0], [%1], 16;"
                     :: "r"(sa), "l"(gsrc + f4 * 4) : "memory");
    }
}

__global__ __launch_bounds__(256, 4) void bilinear_mma_kernel(
    const float* __restrict__ bias, float* __restrict__ out)
{
    extern __shared__ uint32_t sm[];
    uint32_t* Af = sm;
    uint32_t* Bf = sm + TILE_W;
    float* stage = reinterpret_cast<float*>(sm + 2 * TILE_W);

    int t    = threadIdx.x;
    int warp = t >> 5;
    int lane = t & 31;
    int wm   = warp >> 2;      // 0..1  (m, 64 rows)
    int wn   = warp & 3;       // 0..3  (n, 32 cols)
    int g    = lane >> 2;      // 0..7
    int tg   = lane & 3;       // 0..3

    int s  = blockIdx.z;
    int i0 = blockIdx.y * 128;
    int j0 = blockIdx.x * 128;

    size_t abase = (size_t)(s * N_DIM + i0) * (D_DIM / 2);
    size_t bbase = (size_t)(s * N_DIM + j0) * (D_DIM / 2);
    fill_tile_async(g_Xf + abase, Af, t);
    fill_tile_async(g_Qf + bbase, Bf, t);
    asm volatile("cp.async.commit_group;" ::: "memory");
    asm volatile("cp.async.wait_group 0;" ::: "memory");
    __syncthreads();

    // ldmatrix per-lane row addressing (b16 elements)
    int rowA   = (lane & 7) + 8 * ((lane >> 3) & 1);
    int kplusA = (lane >> 4) & 1;
    int rowB   = lane & 7;
    int kplusB = (lane >> 3) & 1;

    uint32_t aAf = smem_u32(Af) + ((wm * 64 + rowA) * PADW + kplusA * 4) * 4;
    uint32_t aBf = smem_u32(Bf) + ((wn * 32 + rowB) * PADW + kplusB * 4) * 4;

    float bv = __ldg(bias);
    const size_t batch_stride = (size_t)S_DIM * N_DIM * N_DIM;

#pragma unroll
    for (int q = 0; q < 4; ++q) {
        // ---- compute quarter: mt = q (rows wm*64 + q*16 .. +15) ----
        float acc[4][4];
#pragma unroll
        for (int b = 0; b < 4; ++b)
#pragma unroll
            for (int c = 0; c < 4; ++c) acc[b][c] = 0.0f;

#pragma unroll
        for (int kt = 0; kt < 4; ++kt) {
            uint32_t af[4];
            uint32_t bf[4][2];
            ldsm_x4(af, aAf + q * A_MT_BYTES + kt * KT_BYTES);
#pragma unroll
            for (int nt = 0; nt < 4; ++nt)
                ldsm_x2(bf[nt], aBf + nt * B_NT_BYTES + kt * KT_BYTES);

#pragma unroll
            for (int nt = 0; nt < 4; ++nt)
                mma_fp16(acc[nt], af, bf[nt]);
        }

        // ---- store quarter via stage (32 rows: wm*16 + g + 8h) ----
        __syncthreads();   // stage free (prev quarter's readers done)
#pragma unroll
        for (int h = 0; h < 2; ++h) {
            int L = wm * 16 + g + 8 * h;
#pragma unroll
            for (int nt = 0; nt < 4; ++nt) {
                float2 v;
                v.x = acc[nt][2 * h + 0] + bv;
                v.y = acc[nt][2 * h + 1] + bv;
                *reinterpret_cast<float2*>(
                    &stage[L * STG_STRIDE + wn * 32 + nt * 8 + 2 * tg]) = v;
            }
        }
        __syncthreads();
        // Coalesced: warp reads full 128-float rows, 512B STG.128 runs
#pragma unroll
        for (int rr = 0; rr < 4; ++rr) {
            int L = warp * 4 + rr;      // 0..31
            int irel = ((L >> 4) << 6) + (q << 4) + (L & 15);
            size_t rowoff = ((size_t)s * N_DIM + i0 + irel) * N_DIM + j0;
            float4 v = *reinterpret_cast<float4*>(&stage[L * STG_STRIDE + lane * 4]);
            __stcs(reinterpret_cast<float4*>(&out[rowoff + lane * 4]), v);
            __stcs(reinterpret_cast<float4*>(&out[rowoff + lane * 4 + batch_stride]), v);
        }
    }
}

extern "C" void kernel_launch(void* const* d_in, const int* in_sizes, int n_in,
                              void* d_out, int out_size)
{
    const float* x0   = (const float*)d_in[0];  // tensor0 (S,N,D)
    const float* x1   = (const float*)d_in[1];  // tensor1 (S,N,D)
    const float* W    = (const float*)d_in[2];  // kernel  (D,D)
    const float* bias = (const float*)d_in[3];  // scalar
    float* out = (float*)d_out;                 // (2,S,N,N)

    cudaFuncSetAttribute(bilinear_mma_kernel,
                         cudaFuncAttributeMaxDynamicSharedMemorySize, SMEM_DYN);

    prep_kernel<<<256 + (S_DIM * N_DIM * D_DIM) / (256 * 4), 256>>>(x0, x1, W);

    dim3 grid(N_DIM / 128, N_DIM / 128, S_DIM);
    bilinear_mma_kernel<<<grid, 256, SMEM_DYN>>>(bias, out);
}

// round 15
// speedup vs baseline: 1.0220x; 1.0220x over previous
#include <cuda_runtime.h>
#include <cuda_fp16.h>
#include <cstdint>

#define S_DIM 4
#define N_DIM 4096
#define D_DIM 64
#define NTILE 4096
#define NCTA  444           // 3 per SM, persistent

// fp16 operand scratch, pair-packed along k: word = (h16 elem 2p | h16 elem 2p+1 << 16)
#define PAIR_WORDS (S_DIM * N_DIM * D_DIM / 2)
__device__ uint32_t g_Xf[PAIR_WORDS];   // x1 as fp16 pairs
__device__ uint32_t g_Qf[PAIR_WORDS];   // Q  as fp16 pairs

__device__ __forceinline__ uint32_t smem_u32(const void* p) {
    uint32_t a;
    asm("{ .reg .u64 t; cvta.to.shared.u64 t, %1; cvt.u32.u64 %0, t; }"
        : "=r"(a) : "l"(p));
    return a;
}
__device__ __forceinline__ uint32_t h2pack(float a, float b) {
    __half2 h = __floats2half2_rn(a, b);
    return *reinterpret_cast<uint32_t*>(&h);
}
// fp16 mma m16n8k16, fp32 accumulate (baseline PTX, valid on compute_103)
__device__ __forceinline__ void mma_fp16(float d[4], const uint32_t a[4], const uint32_t b[2]) {
    asm volatile(
        "mma.sync.aligned.m16n8k16.row.col.f32.f16.f16.f32 "
        "{%0,%1,%2,%3}, {%4,%5,%6,%7}, {%8,%9}, {%0,%1,%2,%3};"
        : "+f"(d[0]), "+f"(d[1]), "+f"(d[2]), "+f"(d[3])
        : "r"(a[0]), "r"(a[1]), "r"(a[2]), "r"(a[3]), "r"(b[0]), "r"(b[1]));
}
__device__ __forceinline__ void ldsm_x4(uint32_t r[4], uint32_t addr) {
    asm volatile("ldmatrix.sync.aligned.m8n8.x4.shared.b16 {%0,%1,%2,%3}, [%4];"
                 : "=r"(r[0]), "=r"(r[1]), "=r"(r[2]), "=r"(r[3]) : "r"(addr));
}
__device__ __forceinline__ void ldsm_x2(uint32_t r[2], uint32_t addr) {
    asm volatile("ldmatrix.sync.aligned.m8n8.x2.shared.b16 {%0,%1}, [%2];"
                 : "=r"(r[0]), "=r"(r[1]) : "r"(addr));
}

// ---------------------------------------------------------------------------
// Fused prep: blocks [0,256) compute Q (fp32 SIMT) -> fp16 pairs;
//             blocks [256,1280) convert x1 -> fp16 pairs.
// ---------------------------------------------------------------------------
__device__ __forceinline__ void load_tile_transposed64(
    const float* __restrict__ gsrc, float* sdst, int t)
{
    const float4* g4 = reinterpret_cast<const float4*>(gsrc);
#pragma unroll
    for (int p = 0; p < 4; ++p) {
        int f4 = p * 256 + t;
        int x  = f4 >> 4;
        int k4 = (f4 & 15) << 2;
        float4 v = g4[f4];
        float vv[4] = {v.x, v.y, v.z, v.w};
#pragma unroll
        for (int q = 0; q < 4; ++q) {
            int k  = k4 + q;
            int c4 = (x >> 2) ^ ((k >> 2) & 15);
            sdst[k * 64 + c4 * 4 + (x & 3)] = vv[q];
        }
    }
}

__global__ __launch_bounds__(256) void prep_kernel(
    const float* __restrict__ x0, const float* __restrict__ x1,
    const float* __restrict__ W)
{
    __shared__ float Xs[64 * 64];
    __shared__ float Ws[64 * 64];
    int t = threadIdx.x;

    if (blockIdx.x >= 256) {
        int i = (blockIdx.x - 256) * 256 + t;     // float4 index = uint2 pair index
        float4 v = reinterpret_cast<const float4*>(x1)[i];
        uint2 p;
        p.x = h2pack(v.x, v.y);
        p.y = h2pack(v.z, v.w);
        reinterpret_cast<uint2*>(g_Xf)[i] = p;
        return;
    }

    int r0 = blockIdx.x * 64;
    load_tile_transposed64(x0 + (size_t)r0 * 64, Xs, t);
    load_tile_transposed64(W, Ws, t);
    __syncthreads();

    int tx = t & 15, ty = t >> 4;
    float acc[4][4] = {};
#pragma unroll
    for (int k = 0; k < 64; ++k) {
        int sw = (k >> 2) & 15;
        float4 a = *reinterpret_cast<const float4*>(&Xs[k * 64 + ((ty ^ sw) << 2)]);
        float4 b = *reinterpret_cast<const float4*>(&Ws[k * 64 + ((tx ^ sw) << 2)]);
        float av[4] = {a.x, a.y, a.z, a.w};
        float bv[4] = {b.x, b.y, b.z, b.w};
#pragma unroll
        for (int ra = 0; ra < 4; ++ra)
#pragma unroll
            for (int rb = 0; rb < 4; ++rb)
                acc[ra][rb] += av[ra] * bv[rb];
    }

#pragma unroll
    for (int ra = 0; ra < 4; ++ra) {
        int r = r0 + ty * 4 + ra;
        uint2 p;
        p.x = h2pack(acc[ra][0], acc[ra][1]);
        p.y = h2pack(acc[ra][2], acc[ra][3]);
        *reinterpret_cast<uint2*>(&g_Qf[r * 32 + 2 * tx]) = p;
    }
}

// ---------------------------------------------------------------------------
// Stage 2: persistent single-pass fp16 mma.sync GEMM, half-outer structure
// (round-13 body). 444 CTAs (3/SM) x 256 threads, each looping tiles strided
// by 444. Next tile's operand fill is issued inside the hf=1 epilogue (after
// all operand reads are ordered by the stage syncs), draining under the STG
// burst -> loop-top wait is near-free. No wave transitions, no tail wave.
// Smem: 2 operand tiles [128][36 pair-words] (36.9 KB) + stage 64x136 fp32
// (34 KB) = 70.9 KB; x3 CTAs = 213 KB.
// ---------------------------------------------------------------------------
#define PADW 36
#define TILE_W (128 * PADW)
#define STG_STRIDE 136                  // floats per staged row (bank-safe)
#define STAGE_FLOATS (64 * STG_STRIDE)
#define SMEM_DYN (2 * TILE_W * 4 + STAGE_FLOATS * 4)
#define A_MT_BYTES (16 * PADW * 4)      // 16 rows
#define B_NT_BYTES (8 * PADW * 4)       // 8 rows
#define KT_BYTES   32                   // 8 pair-words = 16 fp16

__device__ __forceinline__ void fill_tile_async(
    const uint32_t* __restrict__ gsrc, uint32_t* sdst, int t)
{
#pragma unroll
    for (int it = 0; it < 4; ++it) {
        int f4 = it * 256 + t;          // 0..1023 16B chunks (128 rows x 8)
        int r  = f4 >> 3;
        int c4 = f4 & 7;
        uint32_t sa = smem_u32(&sdst[r * PADW + c4 * 4]);
        asm volatile("cp.async.cg.shared.global [%0], [%1], 16;"
                     :: "r"(sa), "l"(gsrc + f4 * 4) : "memory");
    }
}

__device__ __forceinline__ void fill_tile_pair(uint32_t* Af, uint32_t* Bf, int tile, int t)
{
    int s  = tile >> 10;
    int i0 = ((tile >> 5) & 31) << 7;
    int j0 = (tile & 31) << 7;
    size_t abase = (size_t)(s * N_DIM + i0) * (D_DIM / 2);
    size_t bbase = (size_t)(s * N_DIM + j0) * (D_DIM / 2);
    fill_tile_async(g_Xf + abase, Af, t);
    fill_tile_async(g_Qf + bbase, Bf, t);
    asm volatile("cp.async.commit_group;" ::: "memory");
}

__global__ __launch_bounds__(256, 3) void bilinear_mma_kernel(
    const float* __restrict__ bias, float* __restrict__ out)
{
    extern __shared__ uint32_t sm[];
    uint32_t* Af = sm;
    uint32_t* Bf = sm + TILE_W;
    float* stage = reinterpret_cast<float*>(sm + 2 * TILE_W);

    int t    = threadIdx.x;
    int warp = t >> 5;
    int lane = t & 31;
    int wm   = warp >> 2;      // 0..1  (m, 64 rows)
    int wn   = warp & 3;       // 0..3  (n, 32 cols)
    int g    = lane >> 2;      // 0..7
    int tg   = lane & 3;       // 0..3

    // ldmatrix per-lane row addressing (b16 elements)
    int rowA   = (lane & 7) + 8 * ((lane >> 3) & 1);
    int kplusA = (lane >> 4) & 1;
    int rowB   = lane & 7;
    int kplusB = (lane >> 3) & 1;

    uint32_t aAf = smem_u32(Af) + ((wm * 64 + rowA) * PADW + kplusA * 4) * 4;
    uint32_t aBf = smem_u32(Bf) + ((wn * 32 + rowB) * PADW + kplusB * 4) * 4;

    float bv = __ldg(bias);
    const size_t batch_stride = (size_t)S_DIM * N_DIM * N_DIM;

    fill_tile_pair(Af, Bf, blockIdx.x, t);

    for (int tile = blockIdx.x; tile < NTILE; tile += NCTA) {
        int s  = tile >> 10;
        int i0 = ((tile >> 5) & 31) << 7;
        int j0 = (tile & 31) << 7;
        int next = tile + NCTA;

        asm volatile("cp.async.wait_group 0;" ::: "memory");
        __syncthreads();

#pragma unroll
        for (int hf = 0; hf < 2; ++hf) {
            // ---- compute half: mt = 2hf, 2hf+1 ----
            float acc[2][4][4];
#pragma unroll
            for (int a = 0; a < 2; ++a)
#pragma unroll
                for (int b = 0; b < 4; ++b)
#pragma unroll
                    for (int c = 0; c < 4; ++c) acc[a][b][c] = 0.0f;

#pragma unroll
            for (int kt = 0; kt < 4; ++kt) {
                uint32_t af[2][4];
                uint32_t bf[4][2];
#pragma unroll
                for (int m = 0; m < 2; ++m)
                    ldsm_x4(af[m], aAf + (2 * hf + m) * A_MT_BYTES + kt * KT_BYTES);
#pragma unroll
                for (int nt = 0; nt < 4; ++nt)
                    ldsm_x2(bf[nt], aBf + nt * B_NT_BYTES + kt * KT_BYTES);

#pragma unroll
                for (int m = 0; m < 2; ++m)
#pragma unroll
                    for (int nt = 0; nt < 4; ++nt)
                        mma_fp16(acc[m][nt], af[m], bf[nt]);
            }

            // ---- store half via stage ----
            __syncthreads();   // stage free (prev half's readers done);
                               // at hf=1 this also orders ALL operand reads
#pragma unroll
            for (int m = 0; m < 2; ++m) {
#pragma unroll
                for (int h = 0; h < 2; ++h) {
                    int L = wm * 32 + m * 16 + g + 8 * h;
#pragma unroll
                    for (int nt = 0; nt < 4; ++nt) {
                        float2 v;
                        v.x = acc[m][nt][2 * h + 0] + bv;
                        v.y = acc[m][nt][2 * h + 1] + bv;
                        *reinterpret_cast<float2*>(
                            &stage[L * STG_STRIDE + wn * 32 + nt * 8 + 2 * tg]) = v;
                    }
                }
            }
            __syncthreads();

            // hf=1: all warps are past their operand reads (ordered by the
            // stage-free sync above) -> issue next tile's fill here so the
            // cp.async drains under the STG burst below.
            if (hf == 1 && next < NTILE)
                fill_tile_pair(Af, Bf, next, t);

            // Coalesced: warp reads full 128-float rows, 512B STG.128 runs
#pragma unroll
            for (int rr = 0; rr < 8; ++rr) {
                int L = warp + rr * 8;      // 0..63
                int irel = ((L >> 5) << 6) + ((2 * hf + ((L >> 4) & 1)) << 4) + (L & 15);
                size_t rowoff = ((size_t)s * N_DIM + i0 + irel) * N_DIM + j0;
                float4 v = *reinterpret_cast<float4*>(&stage[L * STG_STRIDE + lane * 4]);
                __stcs(reinterpret_cast<float4*>(&out[rowoff + lane * 4]), v);
                __stcs(reinterpret_cast<float4*>(&out[rowoff + lane * 4 + batch_stride]), v);
            }
        }
    }
}

extern "C" void kernel_launch(void* const* d_in, const int* in_sizes, int n_in,
                              void* d_out, int out_size)
{
    const float* x0   = (const float*)d_in[0];  // tensor0 (S,N,D)
    const float* x1   = (const float*)d_in[1];  // tensor1 (S,N,D)
    const float* W    = (const float*)d_in[2];  // kernel  (D,D)
    const float* bias = (const float*)d_in[3];  // scalar
    float* out = (float*)d_out;                 // (2,S,N,N)

    cudaFuncSetAttribute(bilinear_mma_kernel,
                         cudaFuncAttributeMaxDynamicSharedMemorySize, SMEM_DYN);

    prep_kernel<<<256 + (S_DIM * N_DIM * D_DIM) / (256 * 4), 256>>>(x0, x1, W);

    bilinear_mma_kernel<<<NCTA, 256, SMEM_DYN>>>(bias, out);
}

// round 16
// speedup vs baseline: 1.0478x; 1.0252x over previous
#include <cuda_runtime.h>
#include <cuda_fp16.h>
#include <cstdint>

#define S_DIM 4
#define N_DIM 4096
#define D_DIM 64

// fp16 operand scratch, pair-packed along k: word = (h16 elem 2p | h16 elem 2p+1 << 16)
#define PAIR_WORDS (S_DIM * N_DIM * D_DIM / 2)
__device__ uint32_t g_Xf[PAIR_WORDS];   // x1 as fp16 pairs
__device__ uint32_t g_Qf[PAIR_WORDS];   // Q  as fp16 pairs

__device__ __forceinline__ uint32_t smem_u32(const void* p) {
    uint32_t a;
    asm("{ .reg .u64 t; cvta.to.shared.u64 t, %1; cvt.u32.u64 %0, t; }"
        : "=r"(a) : "l"(p));
    return a;
}
__device__ __forceinline__ uint32_t h2pack(float a, float b) {
    __half2 h = __floats2half2_rn(a, b);
    return *reinterpret_cast<uint32_t*>(&h);
}
// fp16 mma m16n8k16, fp32 accumulate (baseline PTX, valid on compute_103)
__device__ __forceinline__ void mma_fp16(float d[4], const uint32_t a[4], const uint32_t b[2]) {
    asm volatile(
        "mma.sync.aligned.m16n8k16.row.col.f32.f16.f16.f32 "
        "{%0,%1,%2,%3}, {%4,%5,%6,%7}, {%8,%9}, {%0,%1,%2,%3};"
        : "+f"(d[0]), "+f"(d[1]), "+f"(d[2]), "+f"(d[3])
        : "r"(a[0]), "r"(a[1]), "r"(a[2]), "r"(a[3]), "r"(b[0]), "r"(b[1]));
}
__device__ __forceinline__ void ldsm_x4(uint32_t r[4], uint32_t addr) {
    asm volatile("ldmatrix.sync.aligned.m8n8.x4.shared.b16 {%0,%1,%2,%3}, [%4];"
                 : "=r"(r[0]), "=r"(r[1]), "=r"(r[2]), "=r"(r[3]) : "r"(addr));
}
__device__ __forceinline__ void ldsm_x2(uint32_t r[2], uint32_t addr) {
    asm volatile("ldmatrix.sync.aligned.m8n8.x2.shared.b16 {%0,%1}, [%2];"
                 : "=r"(r[0]), "=r"(r[1]) : "r"(addr));
}

// ---------------------------------------------------------------------------
// Fused prep: blocks [0,256) compute Q (fp32 SIMT) -> fp16 pairs;
//             blocks [256,768) convert x1 -> fp16 pairs, 2 float4/thread (MLP 2).
// ---------------------------------------------------------------------------
__device__ __forceinline__ void load_tile_transposed64(
    const float* __restrict__ gsrc, float* sdst, int t)
{
    const float4* g4 = reinterpret_cast<const float4*>(gsrc);
#pragma unroll
    for (int p = 0; p < 4; ++p) {
        int f4 = p * 256 + t;
        int x  = f4 >> 4;
        int k4 = (f4 & 15) << 2;
        float4 v = g4[f4];
        float vv[4] = {v.x, v.y, v.z, v.w};
#pragma unroll
        for (int q = 0; q < 4; ++q) {
            int k  = k4 + q;
            int c4 = (x >> 2) ^ ((k >> 2) & 15);
            sdst[k * 64 + c4 * 4 + (x & 3)] = vv[q];
        }
    }
}

__global__ __launch_bounds__(256) void prep_kernel(
    const float* __restrict__ x0, const float* __restrict__ x1,
    const float* __restrict__ W)
{
    __shared__ float Xs[64 * 64];
    __shared__ float Ws[64 * 64];
    int t = threadIdx.x;

    if (blockIdx.x >= 256) {
        // ---- split x1: 2 independent float4s per thread ----
        const float4* src = reinterpret_cast<const float4*>(x1);
        int base = (blockIdx.x - 256) * 512 + t;
        float4 v0 = src[base];
        float4 v1 = src[base + 256];
        uint2 p0, p1;
        p0.x = h2pack(v0.x, v0.y);  p0.y = h2pack(v0.z, v0.w);
        p1.x = h2pack(v1.x, v1.y);  p1.y = h2pack(v1.z, v1.w);
        reinterpret_cast<uint2*>(g_Xf)[base]       = p0;
        reinterpret_cast<uint2*>(g_Xf)[base + 256] = p1;
        return;
    }

    // ---- Q = x0 · Wᵀ, then convert to fp16 pairs ----
    int r0 = blockIdx.x * 64;
    load_tile_transposed64(x0 + (size_t)r0 * 64, Xs, t);
    load_tile_transposed64(W, Ws, t);
    __syncthreads();

    int tx = t & 15, ty = t >> 4;
    float acc[4][4] = {};
#pragma unroll
    for (int k = 0; k < 64; ++k) {
        int sw = (k >> 2) & 15;
        float4 a = *reinterpret_cast<const float4*>(&Xs[k * 64 + ((ty ^ sw) << 2)]);
        float4 b = *reinterpret_cast<const float4*>(&Ws[k * 64 + ((tx ^ sw) << 2)]);
        float av[4] = {a.x, a.y, a.z, a.w};
        float bv[4] = {b.x, b.y, b.z, b.w};
#pragma unroll
        for (int ra = 0; ra < 4; ++ra)
#pragma unroll
            for (int rb = 0; rb < 4; ++rb)
                acc[ra][rb] += av[ra] * bv[rb];
    }

#pragma unroll
    for (int ra = 0; ra < 4; ++ra) {
        int r = r0 + ty * 4 + ra;
        uint2 p;
        p.x = h2pack(acc[ra][0], acc[ra][1]);
        p.y = h2pack(acc[ra][2], acc[ra][3]);
        *reinterpret_cast<uint2*>(&g_Qf[r * 32 + 2 * tx]) = p;
    }
}

// ---------------------------------------------------------------------------
// Stage 2 (round-13 optimum): single-pass fp16 mma.sync GEMM, half-outer.
// CTA = 128x128 C tile, 256 threads = 8 warps (2m x 4n), warp = 64x32.
// Two halves: compute 64 rows -> staged coalesced store, so the second
// half's MMA overlaps the first half's store drain. 32-reg accumulator ->
// 3 CTAs/SM. Plain 4096-CTA grid (persistent variants measured slower).
// Smem: 2 operand tiles [128][36 pair-words] (36.9 KB) + stage 64x136 fp32
// (34 KB) = 70.9 KB; x3 CTAs = 213 KB.
// ---------------------------------------------------------------------------
#define PADW 36
#define TILE_W (128 * PADW)
#define STG_STRIDE 136                  // floats per staged row (bank-safe)
#define STAGE_FLOATS (64 * STG_STRIDE)
#define SMEM_DYN (2 * TILE_W * 4 + STAGE_FLOATS * 4)
#define A_MT_BYTES (16 * PADW * 4)      // 16 rows
#define B_NT_BYTES (8 * PADW * 4)       // 8 rows
#define KT_BYTES   32                   // 8 pair-words = 16 fp16

__device__ __forceinline__ void fill_tile_async(
    const uint32_t* __restrict__ gsrc, uint32_t* sdst, int t)
{
#pragma unroll
    for (int it = 0; it < 4; ++it) {
        int f4 = it * 256 + t;          // 0..1023 16B chunks (128 rows x 8)
        int r  = f4 >> 3;
        int c4 = f4 & 7;
        uint32_t sa = smem_u32(&sdst[r * PADW + c4 * 4]);
        asm volatile("cp.async.cg.shared.global [%0], [%1], 16;"
                     :: "r"(sa), "l"(gsrc + f4 * 4) : "memory");
    }
}

__global__ __launch_bounds__(256, 3) void bilinear_mma_kernel(
    const float* __restrict__ bias, float* __restrict__ out)
{
    extern __shared__ uint32_t sm[];
    uint32_t* Af = sm;
    uint32_t* Bf = sm + TILE_W;
    float* stage = reinterpret_cast<float*>(sm + 2 * TILE_W);

    int t    = threadIdx.x;
    int warp = t >> 5;
    int lane = t & 31;
    int wm   = warp >> 2;      // 0..1  (m, 64 rows)
    int wn   = warp & 3;       // 0..3  (n, 32 cols)
    int g    = lane >> 2;      // 0..7
    int tg   = lane & 3;       // 0..3

    int s  = blockIdx.z;
    int i0 = blockIdx.y * 128;
    int j0 = blockIdx.x * 128;

    size_t abase = (size_t)(s * N_DIM + i0) * (D_DIM / 2);
    size_t bbase = (size_t)(s * N_DIM + j0) * (D_DIM / 2);
    fill_tile_async(g_Xf + abase, Af, t);
    fill_tile_async(g_Qf + bbase, Bf, t);
    asm volatile("cp.async.commit_group;" ::: "memory");
    asm volatile("cp.async.wait_group 0;" ::: "memory");
    __syncthreads();

    // ldmatrix per-lane row addressing (b16 elements)
    int rowA   = (lane & 7) + 8 * ((lane >> 3) & 1);
    int kplusA = (lane >> 4) & 1;
    int rowB   = lane & 7;
    int kplusB = (lane >> 3) & 1;

    uint32_t aAf = smem_u32(Af) + ((wm * 64 + rowA) * PADW + kplusA * 4) * 4;
    uint32_t aBf = smem_u32(Bf) + ((wn * 32 + rowB) * PADW + kplusB * 4) * 4;

    float bv = __ldg(bias);
    const size_t batch_stride = (size_t)S_DIM * N_DIM * N_DIM;

#pragma unroll
    for (int hf = 0; hf < 2; ++hf) {
        // ---- compute half: mt = 2hf, 2hf+1 ----
        float acc[2][4][4];
#pragma unroll
        for (int a = 0; a < 2; ++a)
#pragma unroll
            for (int b = 0; b < 4; ++b)
#pragma unroll
                for (int c = 0; c < 4; ++c) acc[a][b][c] = 0.0f;

#pragma unroll
        for (int kt = 0; kt < 4; ++kt) {
            uint32_t af[2][4];
            uint32_t bf[4][2];
#pragma unroll
            for (int m = 0; m < 2; ++m)
                ldsm_x4(af[m], aAf + (2 * hf + m) * A_MT_BYTES + kt * KT_BYTES);
#pragma unroll
            for (int nt = 0; nt < 4; ++nt)
                ldsm_x2(bf[nt], aBf + nt * B_NT_BYTES + kt * KT_BYTES);

#pragma unroll
            for (int m = 0; m < 2; ++m)
#pragma unroll
                for (int nt = 0; nt < 4; ++nt)
                    mma_fp16(acc[m][nt], af[m], bf[nt]);
        }

        // ---- store half via stage ----
        __syncthreads();   // stage free (prev half's readers done)
#pragma unroll
        for (int m = 0; m < 2; ++m) {
#pragma unroll
            for (int h = 0; h < 2; ++h) {
                int L = wm * 32 + m * 16 + g + 8 * h;
#pragma unroll
                for (int nt = 0; nt < 4; ++nt) {
                    float2 v;
                    v.x = acc[m][nt][2 * h + 0] + bv;
                    v.y = acc[m][nt][2 * h + 1] + bv;
                    *reinterpret_cast<float2*>(
                        &stage[L * STG_STRIDE + wn * 32 + nt * 8 + 2 * tg]) = v;
                }
            }
        }
        __syncthreads();
        // Coalesced: warp reads full 128-float rows, 512B STG.128 runs
#pragma unroll
        for (int rr = 0; rr < 8; ++rr) {
            int L = warp + rr * 8;      // 0..63
            int irel = ((L >> 5) << 6) + ((2 * hf + ((L >> 4) & 1)) << 4) + (L & 15);
            size_t rowoff = ((size_t)s * N_DIM + i0 + irel) * N_DIM + j0;
            float4 v = *reinterpret_cast<float4*>(&stage[L * STG_STRIDE + lane * 4]);
            __stcs(reinterpret_cast<float4*>(&out[rowoff + lane * 4]), v);
            __stcs(reinterpret_cast<float4*>(&out[rowoff + lane * 4 + batch_stride]), v);
        }
    }
}

extern "C" void kernel_launch(void* const* d_in, const int* in_sizes, int n_in,
                              void* d_out, int out_size)
{
    const float* x0   = (const float*)d_in[0];  // tensor0 (S,N,D)
    const float* x1   = (const float*)d_in[1];  // tensor1 (S,N,D)
    const float* W    = (const float*)d_in[2];  // kernel  (D,D)
    const float* bias = (const float*)d_in[3];  // scalar
    float* out = (float*)d_out;                 // (2,S,N,N)

    cudaFuncSetAttribute(bilinear_mma_kernel,
                         cudaFuncAttributeMaxDynamicSharedMemorySize, SMEM_DYN);

    // 256 Q-blocks + 512 x1-split blocks (2 float4/thread)
    prep_kernel<<<768, 256>>>(x0, x1, W);

    dim3 grid(N_DIM / 128, N_DIM / 128, S_DIM);
    bilinear_mma_kernel<<<grid, 256, SMEM_DYN>>>(bias, out);
}